// round 3
// baseline (speedup 1.0000x reference)
#include <cuda_runtime.h>
#include <cstdint>

#define T_NODES 80000          // B*N = 16*5000
#define C_DIM   128
#define HF_DIM  128            // H*F = 2*64
#define E_EDGES 1280000
#define NEG_SLOPE 0.2f
#define SCAN_BLOCKS ((T_NODES + 255) / 256)   // 313

// ---------------- static device scratch ----------------
__device__ __align__(16) float g_xl[T_NODES * HF_DIM];   // 40.96 MB
__device__ __align__(16) float g_xr[T_NODES * HF_DIM];   // 40.96 MB
__device__ int g_deg[T_NODES];
__device__ int g_off[T_NODES + 1];
__device__ int g_cur[T_NODES];
__device__ int g_csr_src[E_EDGES];
__device__ volatile int g_scan_state[SCAN_BLOCKS];  // 0=none,1=agg,2=prefix
__device__ volatile int g_scan_agg[SCAN_BLOCKS];
__device__ volatile int g_scan_pre[SCAN_BLOCKS];

// ---------------- f32x2 packed-FMA helpers ----------------
__device__ __forceinline__ unsigned long long pack2(float v) {
    unsigned long long r;
    asm("mov.b64 %0, {%1, %1};" : "=l"(r) : "f"(v));
    return r;
}
__device__ __forceinline__ void fma2(unsigned long long& c, unsigned long long a,
                                     unsigned long long b) {
    asm("fma.rn.f32x2 %0, %1, %2, %3;" : "=l"(c) : "l"(a), "l"(b), "l"(c));
}
__device__ __forceinline__ float2 unpack2(unsigned long long v) {
    float2 f;
    asm("mov.b64 {%0, %1}, %2;" : "=f"(f.x), "=f"(f.y) : "l"(v));
    return f;
}

// ---------------- K0: zero degree array + scan flags ----------------
__global__ void zero_kernel() {
    int i = blockIdx.x * blockDim.x + threadIdx.x;
    if (i < T_NODES) g_deg[i] = 0;
    if (i < SCAN_BLOCKS) g_scan_state[i] = 0;
}

// ---------------- K1: fused GEMMs + hidden histogram ----------------
// grid (625, 2), 256 threads. Also histograms dst degrees (mem work hides
// under the fma-bound mainloop of other warps).
__global__ void __launch_bounds__(256, 2)
gemm_kernel(const float* __restrict__ X,
            const float* __restrict__ Wl, const float* __restrict__ bl,
            const float* __restrict__ Wr, const float* __restrict__ br,
            const int* __restrict__ ei, int E) {
    __shared__ float As[32][132];
    __shared__ float Bs[32][128];

    const int which = blockIdx.y;
    const float* __restrict__ W    = which ? Wr : Wl;
    const float* __restrict__ bvec = which ? br : bl;
    float* __restrict__ Y = which ? g_xr : g_xl;

    const int t = threadIdx.x;

    // histogram: strided over all edges by this grid's 320000 threads
    {
        const int nthr = gridDim.x * gridDim.y * 256;
        int gid = (blockIdx.y * gridDim.x + blockIdx.x) * 256 + t;
        const int* __restrict__ dsts = ei + E;
        for (int e = gid; e < E; e += nthr)
            atomicAdd(&g_deg[dsts[e]], 1);
    }

    const int tx = t & 15;
    const int ty = t >> 4;
    const int rowBase = blockIdx.x * 128;

    unsigned long long acc[8][4] = {};

#pragma unroll 1
    for (int kc = 0; kc < 128; kc += 32) {
#pragma unroll
        for (int rr = 0; rr < 4; rr++) {
            int r  = rr * 32 + (t >> 3);
            int kq = (t & 7) * 4;
            float4 v = *(const float4*)&X[(size_t)(rowBase + r) * C_DIM + kc + kq];
            As[kq + 0][r] = v.x;
            As[kq + 1][r] = v.y;
            As[kq + 2][r] = v.z;
            As[kq + 3][r] = v.w;
        }
#pragma unroll
        for (int q = 0; q < 4; q++) {
            int fidx = q * 256 + t;
            int k  = fidx >> 5;
            int n4 = (fidx & 31) * 4;
            *(float4*)&Bs[k][n4] = *(const float4*)&W[(size_t)(kc + k) * HF_DIM + n4];
        }
        __syncthreads();

#pragma unroll
        for (int k = 0; k < 32; k++) {
            float4 a0 = *(const float4*)&As[k][ty * 8];
            float4 a1 = *(const float4*)&As[k][ty * 8 + 4];
            ulonglong2 b0 = *(const ulonglong2*)&Bs[k][tx * 8];
            ulonglong2 b1 = *(const ulonglong2*)&Bs[k][tx * 8 + 4];
            unsigned long long ap[8];
            ap[0] = pack2(a0.x); ap[1] = pack2(a0.y);
            ap[2] = pack2(a0.z); ap[3] = pack2(a0.w);
            ap[4] = pack2(a1.x); ap[5] = pack2(a1.y);
            ap[6] = pack2(a1.z); ap[7] = pack2(a1.w);
            unsigned long long bb[4] = { b0.x, b0.y, b1.x, b1.y };
#pragma unroll
            for (int i = 0; i < 8; i++)
#pragma unroll
                for (int j = 0; j < 4; j++)
                    fma2(acc[i][j], ap[i], bb[j]);
        }
        __syncthreads();
    }

#pragma unroll
    for (int i = 0; i < 8; i++) {
        int row = rowBase + ty * 8 + i;
#pragma unroll
        for (int j = 0; j < 4; j++) {
            float2 c = unpack2(acc[i][j]);
            int col = tx * 8 + j * 2;
            Y[(size_t)row * HF_DIM + col]     = c.x + bvec[col];
            Y[(size_t)row * HF_DIM + col + 1] = c.y + bvec[col + 1];
        }
    }
}

// ---------------- K2: single-pass decoupled-lookback scan ----------------
// 313 blocks x 256 — all resident in one wave, lookback cannot deadlock.
__global__ void __launch_bounds__(256)
scan_kernel() {
    const int b = blockIdx.x, t = threadIdx.x;
    const int lane = t & 31, w = t >> 5;
    int i = b * 256 + t;
    int v = (i < T_NODES) ? g_deg[i] : 0;

    // warp inclusive scan
    int x = v;
#pragma unroll
    for (int d = 1; d < 32; d <<= 1) {
        int y = __shfl_up_sync(0xffffffffu, x, d);
        if (lane >= d) x += y;
    }
    __shared__ int wt[8];
    if (lane == 31) wt[w] = x;
    __syncthreads();
    if (t < 8) {
        int y = wt[t];
#pragma unroll
        for (int d = 1; d < 8; d <<= 1) {
            int z = __shfl_up_sync(0x000000ffu, y, d);
            if (t >= d) y += z;
        }
        wt[t] = y;
    }
    __syncthreads();
    int incl  = x + (w ? wt[w - 1] : 0);
    int total = wt[7];

    __shared__ int s_excl;
    if (t == 0) {
        g_scan_agg[b] = total;
        __threadfence();
        g_scan_state[b] = 1;
        int excl = 0;
        if (b > 0) {
            int j = b - 1;
            while (true) {
                int st;
                while ((st = g_scan_state[j]) == 0) { }
                if (st == 2) { excl += g_scan_pre[j]; break; }
                excl += g_scan_agg[j];
                if (--j < 0) break;
            }
        }
        g_scan_pre[b] = excl + total;
        __threadfence();
        g_scan_state[b] = 2;
        s_excl = excl;
    }
    __syncthreads();

    int off = s_excl + incl - v;   // exclusive prefix
    if (i < T_NODES) {
        g_off[i] = off;
        g_cur[i] = off;
        if (i == T_NODES - 1) g_off[T_NODES] = off + v;
    }
}

// ---------------- K3: scatter ----------------
__global__ void scatter_kernel(const int* __restrict__ ei, int E) {
    int e = blockIdx.x * blockDim.x + threadIdx.x;
    if (e < E) {
        int src = ei[e];
        int dst = ei[E + e];
        int pos = atomicAdd(&g_cur[dst], 1);
        g_csr_src[pos] = src;
    }
}

// ---------------- K4: softmax + aggregation (baseline-exp, unroll-4) ----------
__device__ __forceinline__ float edge_logit(float4 xs, float4 xr, float4 av) {
    float t0 = xs.x + xr.x, t1 = xs.y + xr.y, t2 = xs.z + xr.z, t3 = xs.w + xr.w;
    float l0 = fmaxf(t0, 0.f) + NEG_SLOPE * fminf(t0, 0.f);
    float l1 = fmaxf(t1, 0.f) + NEG_SLOPE * fminf(t1, 0.f);
    float l2 = fmaxf(t2, 0.f) + NEG_SLOPE * fminf(t2, 0.f);
    float l3 = fmaxf(t3, 0.f) + NEG_SLOPE * fminf(t3, 0.f);
    float p = l0 * av.x;
    p = fmaf(l1, av.y, p);
    p = fmaf(l2, av.z, p);
    p = fmaf(l3, av.w, p);
    p += __shfl_xor_sync(0xffffffffu, p, 1);
    p += __shfl_xor_sync(0xffffffffu, p, 2);
    p += __shfl_xor_sync(0xffffffffu, p, 4);
    p += __shfl_xor_sync(0xffffffffu, p, 8);
    return p;
}

__global__ void __launch_bounds__(256)
agg_kernel(const float* __restrict__ att, const float* __restrict__ bias,
           float* __restrict__ out) {
    int warp_id = (blockIdx.x * blockDim.x + threadIdx.x) >> 5;
    int lane = threadIdx.x & 31;
    if (warp_id >= T_NODES) return;
    const int d = warp_id;
    const int fbase = lane * 4;

    const float4* __restrict__ xlp = (const float4*)g_xl;
    const float4* __restrict__ xrp = (const float4*)g_xr;

    float4 av  = *(const float4*)&att[fbase];
    float4 xr  = xrp[(size_t)d * 32 + lane];
    float4 xld = xlp[(size_t)d * 32 + lane];

    // self-loop logit is the fixed softmax baseline (shift-invariant)
    const float lself = edge_logit(xld, xr, av);
    float den = 1.0f;
    float4 acc = xld;

    const int beg = g_off[d];
    const int n = g_off[d + 1] - beg;

    if (n > 0) {
        const int* __restrict__ sp = g_csr_src + beg;
        const int nm1 = n - 1;

        // pipeline: x 4-deep, src indices 8-deep (clamped)
        int s4 = __ldg(&sp[min(4, nm1)]);
        int s5 = __ldg(&sp[min(5, nm1)]);
        int s6 = __ldg(&sp[min(6, nm1)]);
        int s7 = __ldg(&sp[min(7, nm1)]);
        float4 x0 = xlp[(size_t)__ldg(&sp[0])           * 32 + lane];
        float4 x1 = xlp[(size_t)__ldg(&sp[min(1, nm1)]) * 32 + lane];
        float4 x2 = xlp[(size_t)__ldg(&sp[min(2, nm1)]) * 32 + lane];
        float4 x3 = xlp[(size_t)__ldg(&sp[min(3, nm1)]) * 32 + lane];

        for (int i = 0; i < n; i += 4) {
            float4 x4 = xlp[(size_t)s4 * 32 + lane];
            float4 x5 = xlp[(size_t)s5 * 32 + lane];
            float4 x6 = xlp[(size_t)s6 * 32 + lane];
            float4 x7 = xlp[(size_t)s7 * 32 + lane];
            s4 = __ldg(&sp[min(i + 8,  nm1)]);
            s5 = __ldg(&sp[min(i + 9,  nm1)]);
            s6 = __ldg(&sp[min(i + 10, nm1)]);
            s7 = __ldg(&sp[min(i + 11, nm1)]);

            float l0 = edge_logit(x0, xr, av);
            float l1 = edge_logit(x1, xr, av);
            float l2 = edge_logit(x2, xr, av);
            float l3 = edge_logit(x3, xr, av);

            float w0 = __expf(l0 - lself);
            float w1 = (i + 1 < n) ? __expf(l1 - lself) : 0.f;
            float w2 = (i + 2 < n) ? __expf(l2 - lself) : 0.f;
            float w3 = (i + 3 < n) ? __expf(l3 - lself) : 0.f;

            den += (w0 + w1) + (w2 + w3);
            acc.x = fmaf(w0, x0.x, fmaf(w1, x1.x, fmaf(w2, x2.x, fmaf(w3, x3.x, acc.x))));
            acc.y = fmaf(w0, x0.y, fmaf(w1, x1.y, fmaf(w2, x2.y, fmaf(w3, x3.y, acc.y))));
            acc.z = fmaf(w0, x0.z, fmaf(w1, x1.z, fmaf(w2, x2.z, fmaf(w3, x3.z, acc.z))));
            acc.w = fmaf(w0, x0.w, fmaf(w1, x1.w, fmaf(w2, x2.w, fmaf(w3, x3.w, acc.w))));

            x0 = x4; x1 = x5; x2 = x6; x3 = x7;
        }
    }

    float inv = 1.0f / den;
    float4 bv = *(const float4*)&bias[fbase];
    float4 r;
    r.x = fmaf(acc.x, inv, bv.x);
    r.y = fmaf(acc.y, inv, bv.y);
    r.z = fmaf(acc.z, inv, bv.z);
    r.w = fmaf(acc.w, inv, bv.w);
    ((float4*)out)[(size_t)d * 32 + lane] = r;
}

// ---------------- launch ----------------
extern "C" void kernel_launch(void* const* d_in, const int* in_sizes, int n_in,
                              void* d_out, int out_size) {
    const float* x    = (const float*)d_in[0];
    const int*   ei   = (const int*)d_in[1];
    const float* Wl   = (const float*)d_in[2];
    const float* bl   = (const float*)d_in[3];
    const float* Wr   = (const float*)d_in[4];
    const float* br   = (const float*)d_in[5];
    const float* att  = (const float*)d_in[6];
    const float* bias = (const float*)d_in[7];
    float* out = (float*)d_out;

    const int E = in_sizes[1] / 2;

    zero_kernel<<<SCAN_BLOCKS, 256>>>();

    dim3 ggrid(T_NODES / 128, 2);
    gemm_kernel<<<ggrid, 256>>>(x, Wl, bl, Wr, br, ei, E);  // hist hidden inside

    scan_kernel<<<SCAN_BLOCKS, 256>>>();
    scatter_kernel<<<(E + 255) / 256, 256>>>(ei, E);
    agg_kernel<<<(T_NODES * 32 + 255) / 256, 256>>>(att, bias, out);
}

// round 4
// speedup vs baseline: 1.0450x; 1.0450x over previous
#include <cuda_runtime.h>
#include <cstdint>

#define T_NODES 80000          // B*N = 16*5000
#define C_DIM   128
#define HF_DIM  128            // H*F = 2*64
#define E_EDGES 1280000
#define NEG_SLOPE 0.2f
#define SCAN_BLOCKS ((T_NODES + 255) / 256)   // 313

// ---------------- static device scratch ----------------
__device__ __align__(16) float g_xl[T_NODES * HF_DIM];   // 40.96 MB
__device__ __align__(16) float g_xr[T_NODES * HF_DIM];   // 40.96 MB
__device__ int g_deg[T_NODES];
__device__ int g_off[T_NODES + 1];
__device__ int g_cur[T_NODES];
__device__ int g_csr_src[E_EDGES];
// packed lookback word: low 2 bits = state (0 none, 1 agg, 2 prefix), high 32 = value
__device__ volatile unsigned long long g_scan_word[SCAN_BLOCKS];

// ---------------- f32x2 packed-FMA helpers ----------------
__device__ __forceinline__ unsigned long long pack2(float v) {
    unsigned long long r;
    asm("mov.b64 %0, {%1, %1};" : "=l"(r) : "f"(v));
    return r;
}
__device__ __forceinline__ void fma2(unsigned long long& c, unsigned long long a,
                                     unsigned long long b) {
    asm("fma.rn.f32x2 %0, %1, %2, %3;" : "=l"(c) : "l"(a), "l"(b), "l"(c));
}
__device__ __forceinline__ float2 unpack2(unsigned long long v) {
    float2 f;
    asm("mov.b64 {%0, %1}, %2;" : "=f"(f.x), "=f"(f.y) : "l"(v));
    return f;
}

// ---------------- K0: zero degree array + scan words ----------------
__global__ void zero_kernel() {
    int i = blockIdx.x * blockDim.x + threadIdx.x;
    if (i < T_NODES) g_deg[i] = 0;
    if (i < SCAN_BLOCKS) g_scan_word[i] = 0ull;
}

// ---------------- K1: fused GEMMs + hidden histogram ----------------
__global__ void __launch_bounds__(256, 2)
gemm_kernel(const float* __restrict__ X,
            const float* __restrict__ Wl, const float* __restrict__ bl,
            const float* __restrict__ Wr, const float* __restrict__ br,
            const int* __restrict__ ei, int E) {
    __shared__ float As[32][132];
    __shared__ float Bs[32][128];

    const int which = blockIdx.y;
    const float* __restrict__ W    = which ? Wr : Wl;
    const float* __restrict__ bvec = which ? br : bl;
    float* __restrict__ Y = which ? g_xr : g_xl;

    const int t = threadIdx.x;

    // histogram (fire-and-forget REDs; no return value -> no latency chain)
    {
        const int nthr = gridDim.x * gridDim.y * 256;
        int gid = (blockIdx.y * gridDim.x + blockIdx.x) * 256 + t;
        const int* __restrict__ dsts = ei + E;
        if ((E & 3) == 0) {
            const int4* __restrict__ d4 = (const int4*)dsts;
            for (int e = gid; e < (E >> 2); e += nthr) {
                int4 v = d4[e];
                atomicAdd(&g_deg[v.x], 1);
                atomicAdd(&g_deg[v.y], 1);
                atomicAdd(&g_deg[v.z], 1);
                atomicAdd(&g_deg[v.w], 1);
            }
        } else {
            for (int e = gid; e < E; e += nthr)
                atomicAdd(&g_deg[dsts[e]], 1);
        }
    }

    const int tx = t & 15;
    const int ty = t >> 4;
    const int rowBase = blockIdx.x * 128;

    unsigned long long acc[8][4] = {};

#pragma unroll 1
    for (int kc = 0; kc < 128; kc += 32) {
#pragma unroll
        for (int rr = 0; rr < 4; rr++) {
            int r  = rr * 32 + (t >> 3);
            int kq = (t & 7) * 4;
            float4 v = *(const float4*)&X[(size_t)(rowBase + r) * C_DIM + kc + kq];
            As[kq + 0][r] = v.x;
            As[kq + 1][r] = v.y;
            As[kq + 2][r] = v.z;
            As[kq + 3][r] = v.w;
        }
#pragma unroll
        for (int q = 0; q < 4; q++) {
            int fidx = q * 256 + t;
            int k  = fidx >> 5;
            int n4 = (fidx & 31) * 4;
            *(float4*)&Bs[k][n4] = *(const float4*)&W[(size_t)(kc + k) * HF_DIM + n4];
        }
        __syncthreads();

#pragma unroll
        for (int k = 0; k < 32; k++) {
            float4 a0 = *(const float4*)&As[k][ty * 8];
            float4 a1 = *(const float4*)&As[k][ty * 8 + 4];
            ulonglong2 b0 = *(const ulonglong2*)&Bs[k][tx * 8];
            ulonglong2 b1 = *(const ulonglong2*)&Bs[k][tx * 8 + 4];
            unsigned long long ap[8];
            ap[0] = pack2(a0.x); ap[1] = pack2(a0.y);
            ap[2] = pack2(a0.z); ap[3] = pack2(a0.w);
            ap[4] = pack2(a1.x); ap[5] = pack2(a1.y);
            ap[6] = pack2(a1.z); ap[7] = pack2(a1.w);
            unsigned long long bb[4] = { b0.x, b0.y, b1.x, b1.y };
#pragma unroll
            for (int i = 0; i < 8; i++)
#pragma unroll
                for (int j = 0; j < 4; j++)
                    fma2(acc[i][j], ap[i], bb[j]);
        }
        __syncthreads();
    }

#pragma unroll
    for (int i = 0; i < 8; i++) {
        int row = rowBase + ty * 8 + i;
#pragma unroll
        for (int j = 0; j < 4; j++) {
            float2 c = unpack2(acc[i][j]);
            int col = tx * 8 + j * 2;
            Y[(size_t)row * HF_DIM + col]     = c.x + bvec[col];
            Y[(size_t)row * HF_DIM + col + 1] = c.y + bvec[col + 1];
        }
    }
}

// ---------------- K2: single-pass scan, WARP-PARALLEL lookback ----------------
__global__ void __launch_bounds__(256)
scan_kernel() {
    const int b = blockIdx.x, t = threadIdx.x;
    const int lane = t & 31, w = t >> 5;
    int i = b * 256 + t;
    int v = (i < T_NODES) ? g_deg[i] : 0;

    // block-local inclusive scan
    int x = v;
#pragma unroll
    for (int d = 1; d < 32; d <<= 1) {
        int y = __shfl_up_sync(0xffffffffu, x, d);
        if (lane >= d) x += y;
    }
    __shared__ int wt[8];
    if (lane == 31) wt[w] = x;
    __syncthreads();
    if (t < 8) {
        int y = wt[t];
#pragma unroll
        for (int d = 1; d < 8; d <<= 1) {
            int z = __shfl_up_sync(0x000000ffu, y, d);
            if (t >= d) y += z;
        }
        wt[t] = y;
    }
    __syncthreads();
    int incl  = x + (w ? wt[w - 1] : 0);
    int total = wt[7];

    __shared__ int s_excl;
    if (w == 0) {
        // publish aggregate (packed: value<<32 | state)
        if (lane == 0)
            g_scan_word[b] = ((unsigned long long)(unsigned)total << 32) | 1ull;

        int excl = 0;
        int base = b - 1;
        while (base >= 0) {
            int idx = base - lane;
            unsigned long long wv = 0; int st = 0;
            if (idx >= 0) {
                do { wv = g_scan_word[idx]; st = (int)(wv & 3ull); } while (st == 0);
            }
            int val = (int)(wv >> 32);
            unsigned pm = __ballot_sync(0xffffffffu, idx >= 0 && st == 2);
            if (pm) {
                int fl = __ffs(pm) - 1;   // nearest predecessor holding a full prefix
                int contrib = (lane <= fl) ? val : 0;
#pragma unroll
                for (int d = 16; d > 0; d >>= 1)
                    contrib += __shfl_xor_sync(0xffffffffu, contrib, d);
                excl += contrib;
                break;
            } else {
                int contrib = (idx >= 0) ? val : 0;
#pragma unroll
                for (int d = 16; d > 0; d >>= 1)
                    contrib += __shfl_xor_sync(0xffffffffu, contrib, d);
                excl += contrib;
                base -= 32;
            }
        }
        if (lane == 0) {
            g_scan_word[b] = ((unsigned long long)(unsigned)(excl + total) << 32) | 2ull;
            s_excl = excl;
        }
    }
    __syncthreads();

    int off = s_excl + incl - v;   // exclusive prefix
    if (i < T_NODES) {
        g_off[i] = off;
        g_cur[i] = off;
        if (i == T_NODES - 1) g_off[T_NODES] = off + v;
    }
}

// ---------------- K3: scatter, 4 edges per thread (MLP=4) ----------------
__global__ void __launch_bounds__(256)
scatter_kernel(const int* __restrict__ ei, int E) {
    int base = (blockIdx.x * 256 + threadIdx.x) * 4;
    if ((E & 3) == 0) {
        if (base < E) {
            int4 s = *(const int4*)(ei + base);
            int4 d = *(const int4*)(ei + E + base);
            int p0 = atomicAdd(&g_cur[d.x], 1);
            int p1 = atomicAdd(&g_cur[d.y], 1);
            int p2 = atomicAdd(&g_cur[d.z], 1);
            int p3 = atomicAdd(&g_cur[d.w], 1);
            g_csr_src[p0] = s.x;
            g_csr_src[p1] = s.y;
            g_csr_src[p2] = s.z;
            g_csr_src[p3] = s.w;
        }
    } else {
        for (int e = base; e < min(base + 4, E); e++) {
            int pos = atomicAdd(&g_cur[ei[E + e]], 1);
            g_csr_src[pos] = ei[e];
        }
    }
}

// ---------------- K4: softmax + aggregation (baseline-exp, unroll-4) ----------
__device__ __forceinline__ float edge_logit(float4 xs, float4 xr, float4 av) {
    float t0 = xs.x + xr.x, t1 = xs.y + xr.y, t2 = xs.z + xr.z, t3 = xs.w + xr.w;
    float l0 = fmaxf(t0, 0.f) + NEG_SLOPE * fminf(t0, 0.f);
    float l1 = fmaxf(t1, 0.f) + NEG_SLOPE * fminf(t1, 0.f);
    float l2 = fmaxf(t2, 0.f) + NEG_SLOPE * fminf(t2, 0.f);
    float l3 = fmaxf(t3, 0.f) + NEG_SLOPE * fminf(t3, 0.f);
    float p = l0 * av.x;
    p = fmaf(l1, av.y, p);
    p = fmaf(l2, av.z, p);
    p = fmaf(l3, av.w, p);
    p += __shfl_xor_sync(0xffffffffu, p, 1);
    p += __shfl_xor_sync(0xffffffffu, p, 2);
    p += __shfl_xor_sync(0xffffffffu, p, 4);
    p += __shfl_xor_sync(0xffffffffu, p, 8);
    return p;
}

__global__ void __launch_bounds__(256)
agg_kernel(const float* __restrict__ att, const float* __restrict__ bias,
           float* __restrict__ out) {
    int warp_id = (blockIdx.x * blockDim.x + threadIdx.x) >> 5;
    int lane = threadIdx.x & 31;
    if (warp_id >= T_NODES) return;
    const int d = warp_id;
    const int fbase = lane * 4;

    const float4* __restrict__ xlp = (const float4*)g_xl;
    const float4* __restrict__ xrp = (const float4*)g_xr;

    float4 av  = *(const float4*)&att[fbase];
    float4 xr  = xrp[(size_t)d * 32 + lane];
    float4 xld = xlp[(size_t)d * 32 + lane];

    const float lself = edge_logit(xld, xr, av);
    float den = 1.0f;
    float4 acc = xld;

    const int beg = g_off[d];
    const int n = g_off[d + 1] - beg;

    if (n > 0) {
        const int* __restrict__ sp = g_csr_src + beg;
        const int nm1 = n - 1;

        int s4 = __ldg(&sp[min(4, nm1)]);
        int s5 = __ldg(&sp[min(5, nm1)]);
        int s6 = __ldg(&sp[min(6, nm1)]);
        int s7 = __ldg(&sp[min(7, nm1)]);
        float4 x0 = xlp[(size_t)__ldg(&sp[0])           * 32 + lane];
        float4 x1 = xlp[(size_t)__ldg(&sp[min(1, nm1)]) * 32 + lane];
        float4 x2 = xlp[(size_t)__ldg(&sp[min(2, nm1)]) * 32 + lane];
        float4 x3 = xlp[(size_t)__ldg(&sp[min(3, nm1)]) * 32 + lane];

        for (int i = 0; i < n; i += 4) {
            float4 x4 = xlp[(size_t)s4 * 32 + lane];
            float4 x5 = xlp[(size_t)s5 * 32 + lane];
            float4 x6 = xlp[(size_t)s6 * 32 + lane];
            float4 x7 = xlp[(size_t)s7 * 32 + lane];
            s4 = __ldg(&sp[min(i + 8,  nm1)]);
            s5 = __ldg(&sp[min(i + 9,  nm1)]);
            s6 = __ldg(&sp[min(i + 10, nm1)]);
            s7 = __ldg(&sp[min(i + 11, nm1)]);

            float l0 = edge_logit(x0, xr, av);
            float l1 = edge_logit(x1, xr, av);
            float l2 = edge_logit(x2, xr, av);
            float l3 = edge_logit(x3, xr, av);

            float w0 = __expf(l0 - lself);
            float w1 = (i + 1 < n) ? __expf(l1 - lself) : 0.f;
            float w2 = (i + 2 < n) ? __expf(l2 - lself) : 0.f;
            float w3 = (i + 3 < n) ? __expf(l3 - lself) : 0.f;

            den += (w0 + w1) + (w2 + w3);
            acc.x = fmaf(w0, x0.x, fmaf(w1, x1.x, fmaf(w2, x2.x, fmaf(w3, x3.x, acc.x))));
            acc.y = fmaf(w0, x0.y, fmaf(w1, x1.y, fmaf(w2, x2.y, fmaf(w3, x3.y, acc.y))));
            acc.z = fmaf(w0, x0.z, fmaf(w1, x1.z, fmaf(w2, x2.z, fmaf(w3, x3.z, acc.z))));
            acc.w = fmaf(w0, x0.w, fmaf(w1, x1.w, fmaf(w2, x2.w, fmaf(w3, x3.w, acc.w))));

            x0 = x4; x1 = x5; x2 = x6; x3 = x7;
        }
    }

    float inv = 1.0f / den;
    float4 bv = *(const float4*)&bias[fbase];
    float4 r;
    r.x = fmaf(acc.x, inv, bv.x);
    r.y = fmaf(acc.y, inv, bv.y);
    r.z = fmaf(acc.z, inv, bv.z);
    r.w = fmaf(acc.w, inv, bv.w);
    ((float4*)out)[(size_t)d * 32 + lane] = r;
}

// ---------------- launch ----------------
extern "C" void kernel_launch(void* const* d_in, const int* in_sizes, int n_in,
                              void* d_out, int out_size) {
    const float* x    = (const float*)d_in[0];
    const int*   ei   = (const int*)d_in[1];
    const float* Wl   = (const float*)d_in[2];
    const float* bl   = (const float*)d_in[3];
    const float* Wr   = (const float*)d_in[4];
    const float* br   = (const float*)d_in[5];
    const float* att  = (const float*)d_in[6];
    const float* bias = (const float*)d_in[7];
    float* out = (float*)d_out;

    const int E = in_sizes[1] / 2;

    zero_kernel<<<SCAN_BLOCKS, 256>>>();

    dim3 ggrid(T_NODES / 128, 2);
    gemm_kernel<<<ggrid, 256>>>(x, Wl, bl, Wr, br, ei, E);

    scan_kernel<<<SCAN_BLOCKS, 256>>>();
    scatter_kernel<<<(E / 4 + 255) / 256, 256>>>(ei, E);
    agg_kernel<<<(T_NODES * 32 + 255) / 256, 256>>>(att, bias, out);
}

// round 5
// speedup vs baseline: 1.1495x; 1.1000x over previous
#include <cuda_runtime.h>
#include <cstdint>

#define T_NODES 80000          // B*N = 16*5000
#define C_DIM   128
#define HF_DIM  128            // H*F = 2*64
#define E_EDGES 1280000
#define NEG_SLOPE 0.2f
#define SCAN_BLOCKS ((T_NODES + 255) / 256)   // 313

// ---------------- static device scratch (zero-initialized at load) ----------------
__device__ __align__(16) float g_xl[T_NODES * HF_DIM];   // 40.96 MB
__device__ __align__(16) float g_xr[T_NODES * HF_DIM];   // 40.96 MB
__device__ int g_deg[T_NODES];            // invariant: zero at kernel_launch entry
__device__ int g_off[T_NODES + 1];
__device__ int g_cur[T_NODES];
__device__ int g_csr_src[E_EDGES];
// packed lookback word: low 2 bits = state (0 none, 1 agg, 2 prefix), high 32 = value
// invariant: zero at kernel_launch entry (rezeroed by scatter_kernel)
__device__ volatile unsigned long long g_scan_word[SCAN_BLOCKS];

// ---------------- f32x2 packed-FMA helpers ----------------
__device__ __forceinline__ unsigned long long pack2(float v) {
    unsigned long long r;
    asm("mov.b64 %0, {%1, %1};" : "=l"(r) : "f"(v));
    return r;
}
__device__ __forceinline__ void fma2(unsigned long long& c, unsigned long long a,
                                     unsigned long long b) {
    asm("fma.rn.f32x2 %0, %1, %2, %3;" : "=l"(c) : "l"(a), "l"(b), "l"(c));
}
__device__ __forceinline__ float2 unpack2(unsigned long long v) {
    float2 f;
    asm("mov.b64 {%0, %1}, %2;" : "=f"(f.x), "=f"(f.y) : "l"(v));
    return f;
}

// ---------------- K1: fused GEMMs + hidden histogram ----------------
// g_deg is guaranteed zero on entry (static init / previous scan_kernel).
__global__ void __launch_bounds__(256, 2)
gemm_kernel(const float* __restrict__ X,
            const float* __restrict__ Wl, const float* __restrict__ bl,
            const float* __restrict__ Wr, const float* __restrict__ br,
            const int* __restrict__ ei, int E) {
    __shared__ float As[32][132];
    __shared__ float Bs[32][128];

    const int which = blockIdx.y;
    const float* __restrict__ W    = which ? Wr : Wl;
    const float* __restrict__ bvec = which ? br : bl;
    float* __restrict__ Y = which ? g_xr : g_xl;

    const int t = threadIdx.x;

    // histogram (fire-and-forget REDs; no return value -> no latency chain)
    {
        const int nthr = gridDim.x * gridDim.y * 256;
        int gid = (blockIdx.y * gridDim.x + blockIdx.x) * 256 + t;
        const int* __restrict__ dsts = ei + E;
        if ((E & 3) == 0) {
            const int4* __restrict__ d4 = (const int4*)dsts;
            for (int e = gid; e < (E >> 2); e += nthr) {
                int4 v = d4[e];
                atomicAdd(&g_deg[v.x], 1);
                atomicAdd(&g_deg[v.y], 1);
                atomicAdd(&g_deg[v.z], 1);
                atomicAdd(&g_deg[v.w], 1);
            }
        } else {
            for (int e = gid; e < E; e += nthr)
                atomicAdd(&g_deg[dsts[e]], 1);
        }
    }

    const int tx = t & 15;
    const int ty = t >> 4;
    const int rowBase = blockIdx.x * 128;

    unsigned long long acc[8][4] = {};

#pragma unroll 1
    for (int kc = 0; kc < 128; kc += 32) {
#pragma unroll
        for (int rr = 0; rr < 4; rr++) {
            int r  = rr * 32 + (t >> 3);
            int kq = (t & 7) * 4;
            float4 v = *(const float4*)&X[(size_t)(rowBase + r) * C_DIM + kc + kq];
            As[kq + 0][r] = v.x;
            As[kq + 1][r] = v.y;
            As[kq + 2][r] = v.z;
            As[kq + 3][r] = v.w;
        }
#pragma unroll
        for (int q = 0; q < 4; q++) {
            int fidx = q * 256 + t;
            int k  = fidx >> 5;
            int n4 = (fidx & 31) * 4;
            *(float4*)&Bs[k][n4] = *(const float4*)&W[(size_t)(kc + k) * HF_DIM + n4];
        }
        __syncthreads();

#pragma unroll
        for (int k = 0; k < 32; k++) {
            float4 a0 = *(const float4*)&As[k][ty * 8];
            float4 a1 = *(const float4*)&As[k][ty * 8 + 4];
            ulonglong2 b0 = *(const ulonglong2*)&Bs[k][tx * 8];
            ulonglong2 b1 = *(const ulonglong2*)&Bs[k][tx * 8 + 4];
            unsigned long long ap[8];
            ap[0] = pack2(a0.x); ap[1] = pack2(a0.y);
            ap[2] = pack2(a0.z); ap[3] = pack2(a0.w);
            ap[4] = pack2(a1.x); ap[5] = pack2(a1.y);
            ap[6] = pack2(a1.z); ap[7] = pack2(a1.w);
            unsigned long long bb[4] = { b0.x, b0.y, b1.x, b1.y };
#pragma unroll
            for (int i = 0; i < 8; i++)
#pragma unroll
                for (int j = 0; j < 4; j++)
                    fma2(acc[i][j], ap[i], bb[j]);
        }
        __syncthreads();
    }

#pragma unroll
    for (int i = 0; i < 8; i++) {
        int row = rowBase + ty * 8 + i;
#pragma unroll
        for (int j = 0; j < 4; j++) {
            float2 c = unpack2(acc[i][j]);
            int col = tx * 8 + j * 2;
            Y[(size_t)row * HF_DIM + col]     = c.x + bvec[col];
            Y[(size_t)row * HF_DIM + col + 1] = c.y + bvec[col + 1];
        }
    }
}

// ---------------- K2: single-pass scan (warp-parallel lookback) ---------------
// Also re-zeroes g_deg for the next kernel_launch invocation.
__global__ void __launch_bounds__(256)
scan_kernel() {
    const int b = blockIdx.x, t = threadIdx.x;
    const int lane = t & 31, w = t >> 5;
    int i = b * 256 + t;
    int v = (i < T_NODES) ? g_deg[i] : 0;
    if (i < T_NODES) g_deg[i] = 0;          // self-clean for next launch

    // block-local inclusive scan
    int x = v;
#pragma unroll
    for (int d = 1; d < 32; d <<= 1) {
        int y = __shfl_up_sync(0xffffffffu, x, d);
        if (lane >= d) x += y;
    }
    __shared__ int wt[8];
    if (lane == 31) wt[w] = x;
    __syncthreads();
    if (t < 8) {
        int y = wt[t];
#pragma unroll
        for (int d = 1; d < 8; d <<= 1) {
            int z = __shfl_up_sync(0x000000ffu, y, d);
            if (t >= d) y += z;
        }
        wt[t] = y;
    }
    __syncthreads();
    int incl  = x + (w ? wt[w - 1] : 0);
    int total = wt[7];

    __shared__ int s_excl;
    if (w == 0) {
        if (lane == 0)
            g_scan_word[b] = ((unsigned long long)(unsigned)total << 32) | 1ull;

        int excl = 0;
        int base = b - 1;
        while (base >= 0) {
            int idx = base - lane;
            unsigned long long wv = 0; int st = 0;
            if (idx >= 0) {
                do { wv = g_scan_word[idx]; st = (int)(wv & 3ull); } while (st == 0);
            }
            int val = (int)(wv >> 32);
            unsigned pm = __ballot_sync(0xffffffffu, idx >= 0 && st == 2);
            if (pm) {
                int fl = __ffs(pm) - 1;
                int contrib = (lane <= fl) ? val : 0;
#pragma unroll
                for (int d = 16; d > 0; d >>= 1)
                    contrib += __shfl_xor_sync(0xffffffffu, contrib, d);
                excl += contrib;
                break;
            } else {
                int contrib = (idx >= 0) ? val : 0;
#pragma unroll
                for (int d = 16; d > 0; d >>= 1)
                    contrib += __shfl_xor_sync(0xffffffffu, contrib, d);
                excl += contrib;
                base -= 32;
            }
        }
        if (lane == 0) {
            g_scan_word[b] = ((unsigned long long)(unsigned)(excl + total) << 32) | 2ull;
            s_excl = excl;
        }
    }
    __syncthreads();

    int off = s_excl + incl - v;
    if (i < T_NODES) {
        g_off[i] = off;
        g_cur[i] = off;
        if (i == T_NODES - 1) g_off[T_NODES] = off + v;
    }
}

// ---------------- K3: scatter (also re-zeroes scan words) ----------------
__global__ void __launch_bounds__(256)
scatter_kernel(const int* __restrict__ ei, int E) {
    int tid = blockIdx.x * 256 + threadIdx.x;
    if (tid < SCAN_BLOCKS) g_scan_word[tid] = 0ull;   // self-clean for next launch

    int base = tid * 4;
    if ((E & 3) == 0) {
        if (base < E) {
            int4 s = *(const int4*)(ei + base);
            int4 d = *(const int4*)(ei + E + base);
            int p0 = atomicAdd(&g_cur[d.x], 1);
            int p1 = atomicAdd(&g_cur[d.y], 1);
            int p2 = atomicAdd(&g_cur[d.z], 1);
            int p3 = atomicAdd(&g_cur[d.w], 1);
            g_csr_src[p0] = s.x;
            g_csr_src[p1] = s.y;
            g_csr_src[p2] = s.z;
            g_csr_src[p3] = s.w;
        }
    } else {
        for (int e = base; e < min(base + 4, E); e++) {
            int pos = atomicAdd(&g_cur[ei[E + e]], 1);
            g_csr_src[pos] = ei[e];
        }
    }
}

// ---------------- K4: softmax + aggregation (baseline-exp, unroll-2) ----------
__device__ __forceinline__ float edge_logit(float4 xs, float4 xr, float4 av) {
    float t0 = xs.x + xr.x, t1 = xs.y + xr.y, t2 = xs.z + xr.z, t3 = xs.w + xr.w;
    float l0 = fmaxf(t0, 0.f) + NEG_SLOPE * fminf(t0, 0.f);
    float l1 = fmaxf(t1, 0.f) + NEG_SLOPE * fminf(t1, 0.f);
    float l2 = fmaxf(t2, 0.f) + NEG_SLOPE * fminf(t2, 0.f);
    float l3 = fmaxf(t3, 0.f) + NEG_SLOPE * fminf(t3, 0.f);
    float p = l0 * av.x;
    p = fmaf(l1, av.y, p);
    p = fmaf(l2, av.z, p);
    p = fmaf(l3, av.w, p);
    p += __shfl_xor_sync(0xffffffffu, p, 1);
    p += __shfl_xor_sync(0xffffffffu, p, 2);
    p += __shfl_xor_sync(0xffffffffu, p, 4);
    p += __shfl_xor_sync(0xffffffffu, p, 8);
    return p;
}

__global__ void __launch_bounds__(256, 4)
agg_kernel(const float* __restrict__ att, const float* __restrict__ bias,
           float* __restrict__ out) {
    int warp_id = (blockIdx.x * blockDim.x + threadIdx.x) >> 5;
    int lane = threadIdx.x & 31;
    if (warp_id >= T_NODES) return;
    const int d = warp_id;
    const int fbase = lane * 4;

    const float4* __restrict__ xlp = (const float4*)g_xl;
    const float4* __restrict__ xrp = (const float4*)g_xr;

    float4 av  = *(const float4*)&att[fbase];
    float4 xr  = xrp[(size_t)d * 32 + lane];
    float4 xld = xlp[(size_t)d * 32 + lane];

    // self-loop logit is the fixed softmax baseline (shift-invariant)
    const float lself = edge_logit(xld, xr, av);
    float den = 1.0f;
    float4 acc = xld;

    const int beg = g_off[d];
    const int n = g_off[d + 1] - beg;

    if (n > 0) {
        const int* __restrict__ sp = g_csr_src + beg;
        const int nm1 = n - 1;
        // pipeline: x loaded 2-deep, src indices 4-deep (clamped)
        int s2 = __ldg(&sp[min(2, nm1)]);
        int s3 = __ldg(&sp[min(3, nm1)]);
        float4 x0 = xlp[(size_t)__ldg(&sp[0]) * 32 + lane];
        float4 x1 = xlp[(size_t)__ldg(&sp[min(1, nm1)]) * 32 + lane];

        for (int i = 0; i < n; i += 2) {
            float4 x2 = xlp[(size_t)s2 * 32 + lane];
            float4 x3 = xlp[(size_t)s3 * 32 + lane];
            int s4 = __ldg(&sp[min(i + 4, nm1)]);
            int s5 = __ldg(&sp[min(i + 5, nm1)]);

            float l0 = edge_logit(x0, xr, av);
            float l1 = edge_logit(x1, xr, av);
            float w0 = __expf(l0 - lself);
            float w1 = (i + 1 < n) ? __expf(l1 - lself) : 0.f;

            den += w0 + w1;
            acc.x = fmaf(w0, x0.x, fmaf(w1, x1.x, acc.x));
            acc.y = fmaf(w0, x0.y, fmaf(w1, x1.y, acc.y));
            acc.z = fmaf(w0, x0.z, fmaf(w1, x1.z, acc.z));
            acc.w = fmaf(w0, x0.w, fmaf(w1, x1.w, acc.w));

            x0 = x2; x1 = x3;
            s2 = s4; s3 = s5;
        }
    }

    float inv = 1.0f / den;
    float4 bv = *(const float4*)&bias[fbase];
    float4 r;
    r.x = fmaf(acc.x, inv, bv.x);
    r.y = fmaf(acc.y, inv, bv.y);
    r.z = fmaf(acc.z, inv, bv.z);
    r.w = fmaf(acc.w, inv, bv.w);
    ((float4*)out)[(size_t)d * 32 + lane] = r;
}

// ---------------- launch (4 kernels; agg is launch #4 -> ncu profiles it) -----
extern "C" void kernel_launch(void* const* d_in, const int* in_sizes, int n_in,
                              void* d_out, int out_size) {
    const float* x    = (const float*)d_in[0];
    const int*   ei   = (const int*)d_in[1];
    const float* Wl   = (const float*)d_in[2];
    const float* bl   = (const float*)d_in[3];
    const float* Wr   = (const float*)d_in[4];
    const float* br   = (const float*)d_in[5];
    const float* att  = (const float*)d_in[6];
    const float* bias = (const float*)d_in[7];
    float* out = (float*)d_out;

    const int E = in_sizes[1] / 2;

    dim3 ggrid(T_NODES / 128, 2);
    gemm_kernel<<<ggrid, 256>>>(x, Wl, bl, Wr, br, ei, E);  // hist hidden inside

    scan_kernel<<<SCAN_BLOCKS, 256>>>();                    // zeroes g_deg
    scatter_kernel<<<(E / 4 + 255) / 256, 256>>>(ei, E);    // zeroes scan words
    agg_kernel<<<(T_NODES * 32 + 255) / 256, 256>>>(att, bias, out);
}